// round 1
// baseline (speedup 1.0000x reference)
#include <cuda_runtime.h>
#include <cuda_bf16.h>

#define ROI_OUT 7
#define GRIDPTS 14          // 7 bins * 2 samples per axis
#define CCH 256             // channels
#define NROI 1024           // B*N = 4*256
#define NPERB 256

__global__ __launch_bounds__(256) void msroi_kernel(
    const float* __restrict__ f0, const float* __restrict__ f1,
    const float* __restrict__ f2, const float* __restrict__ f3,
    const float* __restrict__ f4, const float* __restrict__ rois,
    float* __restrict__ out)
{
    const int roi_id = blockIdx.x;         // 0..1023 == b*N + n
    const int b      = roi_id >> 8;        // N = 256
    const int tid    = threadIdx.x;

    // ---- ROI params (computed redundantly by all threads; cheap, L1-hit) ----
    const float rx1 = rois[roi_id * 4 + 0];
    const float ry1 = rois[roi_id * 4 + 1];
    const float rx2 = rois[roi_id * 4 + 2];
    const float ry2 = rois[roi_id * 4 + 3];

    // Level selection — must match jnp float32 math.
    float area = (rx2 - rx1) * (ry2 - ry1);
    float lv = floorf(4.0f + log2f(sqrtf(area) / 224.0f + 1e-6f));
    lv = fminf(fmaxf(lv, 2.0f), 6.0f);
    const int lvl = (int)lv - 2;           // feat index 0..4

    const float* feat; int H; float scale;
    switch (lvl) {
        case 0:  feat = f0; H = 128; scale = 0.25f;     break;
        case 1:  feat = f1; H = 64;  scale = 0.125f;    break;
        case 2:  feat = f2; H = 32;  scale = 0.0625f;   break;
        case 3:  feat = f3; H = 16;  scale = 0.03125f;  break;
        default: feat = f4; H = 8;   scale = 0.015625f; break;
    }
    const int W = H;
    const float x1 = rx1 * scale, y1 = ry1 * scale;
    const float roi_w = fmaxf(rx2 * scale - x1, 1.0f);
    const float roi_h = fmaxf(ry2 * scale - y1, 1.0f);
    const float bin_w = roi_w * (1.0f / ROI_OUT);
    const float bin_h = roi_h * (1.0f / ROI_OUT);

    // ---- Per-axis sample tables, shared across all 256 channels ----
    // valid = vy & vx folds exactly into the separable weights (v in {0,1}).
    __shared__ int   sxi0[GRIDPTS], sxi1[GRIDPTS];     // x tap indices
    __shared__ int   syo0[GRIDPTS], syo1[GRIDPTS];     // y tap row offsets (y*W)
    __shared__ float swx0[GRIDPTS], swx1[GRIDPTS];
    __shared__ float swy0[GRIDPTS], swy1[GRIDPTS];

    if (tid < 2 * GRIDPTS) {
        const bool isY = (tid >= GRIDPTS);
        const int  i   = isY ? tid - GRIDPTS : tid;
        // reference grid: k + (sr+0.5)/2  ==  0.25 + 0.5*gi (exact in fp32)
        const float g = 0.25f + 0.5f * (float)i;
        const float p = isY ? (y1 + g * bin_h) : (x1 + g * bin_w);
        const float v = (p >= -1.0f && p <= (float)H) ? 1.0f : 0.0f;
        const float pc  = fminf(fmaxf(p, 0.0f), (float)(H - 1));
        const float p0f = floorf(pc);
        const float l   = pc - p0f;
        const int p0 = (int)p0f;
        const int p1 = min(p0 + 1, H - 1);
        if (isY) { syo0[i] = p0 * W; syo1[i] = p1 * W;
                   swy0[i] = (1.0f - l) * v; swy1[i] = l * v; }
        else     { sxi0[i] = p0; sxi1[i] = p1;
                   swx0[i] = (1.0f - l) * v; swx1[i] = l * v; }
    }
    __syncthreads();

    const int   HW    = H * W;
    const long  fbase = (long)(b * CCH) * HW;
    float* __restrict__ outp = out + (long)roi_id * (CCH * 49);

    // ---- Hot loop: 49 iterations/thread, pure LDG + FMA ----
    for (int u = tid; u < CCH * 49; u += 256) {
        const int c   = u / 49;
        const int bin = u - c * 49;
        const int oy  = bin / 7;
        const int ox  = bin - oy * 7;
        const float* __restrict__ cp = feat + fbase + (long)c * HW;

        float acc = 0.0f;
        #pragma unroll
        for (int sy = 0; sy < 2; sy++) {
            const int   gy  = 2 * oy + sy;
            const int   yo0 = syo0[gy], yo1 = syo1[gy];
            const float wy0 = swy0[gy], wy1 = swy1[gy];
            #pragma unroll
            for (int sx = 0; sx < 2; sx++) {
                const int   gx  = 2 * ox + sx;
                const int   xi0 = sxi0[gx], xi1 = sxi1[gx];
                const float wx0 = swx0[gx], wx1 = swx1[gx];
                acc += wy0 * (wx0 * __ldg(cp + yo0 + xi0) + wx1 * __ldg(cp + yo0 + xi1))
                     + wy1 * (wx0 * __ldg(cp + yo1 + xi0) + wx1 * __ldg(cp + yo1 + xi1));
            }
        }
        outp[u] = acc * 0.25f;   // mean over 2x2 samples
    }
}

extern "C" void kernel_launch(void* const* d_in, const int* in_sizes, int n_in,
                              void* d_out, int out_size) {
    const float* f0   = (const float*)d_in[0];
    const float* f1   = (const float*)d_in[1];
    const float* f2   = (const float*)d_in[2];
    const float* f3   = (const float*)d_in[3];
    const float* f4   = (const float*)d_in[4];
    const float* rois = (const float*)d_in[5];
    float* out        = (float*)d_out;

    msroi_kernel<<<NROI, 256>>>(f0, f1, f2, f3, f4, rois, out);
}

// round 2
// speedup vs baseline: 1.5893x; 1.5893x over previous
#include <cuda_runtime.h>
#include <cuda_bf16.h>

#define OUTB 49
#define GRIDPTS 14

// Channels-last scratch layout: per level [B][H][W][256]. Bases in floats.
#define FB0 0
#define FB1 16777216            // + 4*256*128*128
#define FB2 20971520            // + 4*256*64*64
#define FB3 22020096            // + 4*256*32*32
#define FB4 22282240            // + 4*256*16*16
#define FT_TOTAL 22347776       // + 4*256*8*8

__device__ float g_ft[FT_TOTAL];   // ~85 MB scratch (static, allowed)

// ---------------- feature transpose: [B,256,H,W] -> [B,H,W,256] ----------------
template<int H>
__global__ __launch_bounds__(256) void transpose_big(const float* __restrict__ in, int obase) {
    __shared__ float tile[32][33];
    const int x0 = blockIdx.x * 32;
    const int c0 = blockIdx.y * 32;
    const int b  = blockIdx.z / H;
    const int y  = blockIdx.z % H;
    const int tx = threadIdx.x, ty = threadIdx.y;

    const float* ip = in + (((long)(b * 256 + c0) * H + y) * H) + x0;
    #pragma unroll
    for (int j = 0; j < 4; j++)
        tile[ty + 8*j][tx] = ip[(long)(ty + 8*j) * (H*H) + tx];
    __syncthreads();

    float* op = g_ft + obase + (((long)(b * H + y) * H) + x0) * 256 + c0;
    #pragma unroll
    for (int j = 0; j < 4; j++)
        op[(ty + 8*j) * 256 + tx] = tile[tx][ty + 8*j];
}

__global__ __launch_bounds__(256) void transpose_small(const float* __restrict__ in, int obase, int H) {
    const int idx = blockIdx.x * 256 + threadIdx.x;     // over B*H*H*256
    const int c = idx & 255;
    const int r = idx >> 8;                             // b*H*H + y*H + x
    const int x = r % H;
    const int t = r / H;
    const int y = t % H;
    const int b = t / H;
    g_ft[obase + idx] = in[((long)(b * 256 + c) * H + y) * H + x];
}

// ---------------- main kernel: block = ROI, lanes = channel quads ----------------
__global__ __launch_bounds__(256) void msroi2(const float* __restrict__ rois, float* __restrict__ out) {
    const int roi = blockIdx.x;         // b*256 + n
    const int b   = roi >> 8;
    const int tid = threadIdx.x;

    __shared__ int   sxo0[GRIDPTS], sxo1[GRIDPTS];   // x tap offsets (x*256)
    __shared__ int   syo0[GRIDPTS], syo1[GRIDPTS];   // y tap row offsets (abs, incl. base & batch)
    __shared__ float swx0[GRIDPTS], swx1[GRIDPTS];
    __shared__ float swy0[GRIDPTS], swy1[GRIDPTS];
    __shared__ float sbuf[OUTB * 68];                 // 64-ch output tile, pitch 68 (16B-aligned, few conflicts)

    // ROI params (redundant per-thread, cheap)
    const float rx1 = rois[roi*4+0], ry1 = rois[roi*4+1];
    const float rx2 = rois[roi*4+2], ry2 = rois[roi*4+3];
    const float area = (rx2 - rx1) * (ry2 - ry1);
    float lv = floorf(4.0f + log2f(sqrtf(area) / 224.0f + 1e-6f));
    lv = fminf(fmaxf(lv, 2.0f), 6.0f);
    const int lvl = (int)lv - 2;

    int H, base; float scale;
    switch (lvl) {
        case 0:  H = 128; base = FB0; scale = 0.25f;     break;
        case 1:  H = 64;  base = FB1; scale = 0.125f;    break;
        case 2:  H = 32;  base = FB2; scale = 0.0625f;   break;
        case 3:  H = 16;  base = FB3; scale = 0.03125f;  break;
        default: H = 8;   base = FB4; scale = 0.015625f; break;
    }
    const float x1 = rx1 * scale, y1 = ry1 * scale;
    const float bw = fmaxf(rx2 * scale - x1, 1.0f) * (1.0f / 7.0f);
    const float bh = fmaxf(ry2 * scale - y1, 1.0f) * (1.0f / 7.0f);

    if (tid < 2 * GRIDPTS) {
        const bool isY = tid >= GRIDPTS;
        const int  i   = isY ? tid - GRIDPTS : tid;
        const float g = 0.25f + 0.5f * (float)i;                 // == k + (sr+0.5)/2
        const float p = isY ? (y1 + g * bh) : (x1 + g * bw);
        const float v = (p >= -1.0f && p <= (float)H) ? 0.5f : 0.0f;  // validity, 0.5*0.5 folds the 2x2 mean
        const float pc = fminf(fmaxf(p, 0.0f), (float)(H - 1));
        const float pf = floorf(pc);
        const float l  = pc - pf;
        const int p0 = (int)pf;
        const int p1 = min(p0 + 1, H - 1);
        if (isY) {
            syo0[i] = base + ((b * H + p0) * H) * 256;
            syo1[i] = base + ((b * H + p1) * H) * 256;
            swy0[i] = (1.0f - l) * v;  swy1[i] = l * v;
        } else {
            sxo0[i] = p0 * 256;  sxo1[i] = p1 * 256;
            swx0[i] = (1.0f - l) * v;  swx1[i] = l * v;
        }
    }
    __syncthreads();

    const int c4 = (tid & 15) * 4;   // channel quad within a 64-ch tile
    const int bg = tid >> 4;         // 16 bin groups

    for (int ct = 0; ct < 4; ct++) {
        const int cofs = ct * 64 + c4;

        for (int bin = bg; bin < OUTB; bin += 16) {
            const int oy = bin / 7;
            const int ox = bin - oy * 7;
            float ax = 0.f, ay = 0.f, az = 0.f, aw = 0.f;
            #pragma unroll
            for (int sy = 0; sy < 2; sy++) {
                const int gy = 2 * oy + sy;
                const int r0 = syo0[gy] + cofs;
                const int r1 = syo1[gy] + cofs;
                const float wy0 = swy0[gy], wy1 = swy1[gy];
                #pragma unroll
                for (int sx = 0; sx < 2; sx++) {
                    const int gx = 2 * ox + sx;
                    const int xo0 = sxo0[gx], xo1 = sxo1[gx];
                    const float w00 = wy0 * swx0[gx];
                    const float w01 = wy0 * swx1[gx];
                    const float w10 = wy1 * swx0[gx];
                    const float w11 = wy1 * swx1[gx];
                    const float4 t00 = *(const float4*)(g_ft + r0 + xo0);
                    const float4 t01 = *(const float4*)(g_ft + r0 + xo1);
                    const float4 t10 = *(const float4*)(g_ft + r1 + xo0);
                    const float4 t11 = *(const float4*)(g_ft + r1 + xo1);
                    ax += w00*t00.x + w01*t01.x + w10*t10.x + w11*t11.x;
                    ay += w00*t00.y + w01*t01.y + w10*t10.y + w11*t11.y;
                    az += w00*t00.z + w01*t01.z + w10*t10.z + w11*t11.z;
                    aw += w00*t00.w + w01*t01.w + w10*t10.w + w11*t11.w;
                }
            }
            *(float4*)(sbuf + bin * 68 + c4) = make_float4(ax, ay, az, aw);
        }
        __syncthreads();

        // coalesced rewrite of this 64-channel tile into [c][bin] order
        float* op = out + roi * (256 * OUTB) + ct * (64 * OUTB);
        for (int o = tid; o < 64 * OUTB; o += 256) {
            const int cc = o / OUTB;
            const int bb = o - cc * OUTB;
            op[o] = sbuf[bb * 68 + cc];
        }
        __syncthreads();
    }
}

extern "C" void kernel_launch(void* const* d_in, const int* in_sizes, int n_in,
                              void* d_out, int out_size) {
    const float* f0   = (const float*)d_in[0];
    const float* f1   = (const float*)d_in[1];
    const float* f2   = (const float*)d_in[2];
    const float* f3   = (const float*)d_in[3];
    const float* f4   = (const float*)d_in[4];
    const float* rois = (const float*)d_in[5];
    float* out        = (float*)d_out;

    transpose_big<128><<<dim3(4, 8, 4 * 128), dim3(32, 8)>>>(f0, FB0);
    transpose_big<64> <<<dim3(2, 8, 4 * 64),  dim3(32, 8)>>>(f1, FB1);
    transpose_big<32> <<<dim3(1, 8, 4 * 32),  dim3(32, 8)>>>(f2, FB2);
    transpose_small<<<1024, 256>>>(f3, FB3, 16);
    transpose_small<<<256,  256>>>(f4, FB4, 8);
    msroi2<<<1024, 256>>>(rois, out);
}